// round 1
// baseline (speedup 1.0000x reference)
#include <cuda_runtime.h>
#include <cuda_bf16.h>
#include <math_constants.h>

#define HW    2304
#define CDIM  512
#define BATCH 8
#define TM    128
#define TN    128
#define KT    8

// Fine path: for bank q in {global_bg, global_fg, local_bg, local_fg},
// out[b, q, n] = max_m ( (bank[b,m,:] . key[b,:,n]) * (mask[b,m,n] if q>=2) )
// One block = one (batch, bank, 128-query tile). Loops over 18 memory tiles,
// doing a 128x128x512 fp32 GEMM tile with fused mask + running column max.
__global__ __launch_bounds__(256, 2) void fine_kernel(
    const float* __restrict__ key,   // [B, C, HW]
    const float* __restrict__ sds,   // [B, HW, HW]
    const float* __restrict__ gbg,   // [B, HW, C]
    const float* __restrict__ gfg,
    const float* __restrict__ lbg,
    const float* __restrict__ lfg,
    float* __restrict__ out)         // [B, 10, HW]
{
    const int ntile = blockIdx.x;    // 0..17
    const int q     = blockIdx.y;    // 0..3
    const int b     = blockIdx.z;    // 0..7

    const float* bank = (q == 0) ? gbg : (q == 1) ? gfg : (q == 2) ? lbg : lfg;
    bank += (size_t)b * HW * CDIM;
    const float* k    = key + (size_t)b * CDIM * HW;
    const float* mask = sds + (size_t)b * HW * HW;
    const bool use_mask = (q >= 2);

    __shared__ float As[KT][TM];     // A^T tile: As[c][m]
    __shared__ float Bs[KT][TN];     // Bs[c][n]
    __shared__ float red[16][TN];

    const int tid = threadIdx.x;
    const int tx  = tid & 15;        // column group (8 cols)
    const int ty  = tid >> 4;        // row group (8 rows)
    const int n0  = ntile * TN;

    float colmax[8];
    #pragma unroll
    for (int j = 0; j < 8; j++) colmax[j] = -CUDART_INF_F;

    // A-tile load coords (fixed per thread)
    const int a_m  = tid >> 1;            // 0..127
    const int a_c4 = (tid & 1) * 4;       // 0 or 4
    // B-tile load coords
    const int b_c  = tid >> 5;            // 0..7
    const int b_n4 = (tid & 31) * 4;      // 0..124

    for (int m0 = 0; m0 < HW; m0 += TM) {
        float acc[8][8];
        #pragma unroll
        for (int i = 0; i < 8; i++)
            #pragma unroll
            for (int j = 0; j < 8; j++) acc[i][j] = 0.0f;

        for (int kk = 0; kk < CDIM; kk += KT) {
            // Load A tile (transposed into smem)
            float4 av = *(const float4*)&bank[(size_t)(m0 + a_m) * CDIM + kk + a_c4];
            As[a_c4 + 0][a_m] = av.x;
            As[a_c4 + 1][a_m] = av.y;
            As[a_c4 + 2][a_m] = av.z;
            As[a_c4 + 3][a_m] = av.w;
            // Load B tile
            *(float4*)&Bs[b_c][b_n4] =
                *(const float4*)&k[(size_t)(kk + b_c) * HW + n0 + b_n4];
            __syncthreads();

            #pragma unroll
            for (int p = 0; p < KT; p++) {
                float a[8], bb[8];
                #pragma unroll
                for (int i = 0; i < 8; i += 4) {
                    float4 v = *(const float4*)&As[p][ty * 8 + i];
                    a[i] = v.x; a[i+1] = v.y; a[i+2] = v.z; a[i+3] = v.w;
                }
                #pragma unroll
                for (int j = 0; j < 8; j += 4) {
                    float4 v = *(const float4*)&Bs[p][tx * 8 + j];
                    bb[j] = v.x; bb[j+1] = v.y; bb[j+2] = v.z; bb[j+3] = v.w;
                }
                #pragma unroll
                for (int i = 0; i < 8; i++)
                    #pragma unroll
                    for (int j = 0; j < 8; j++)
                        acc[i][j] = fmaf(a[i], bb[j], acc[i][j]);
            }
            __syncthreads();
        }

        // Fused epilogue: mask multiply (local banks) + fold rows into column max
        if (use_mask) {
            #pragma unroll
            for (int i = 0; i < 8; i++) {
                const float* mrow = mask + (size_t)(m0 + ty * 8 + i) * HW + n0 + tx * 8;
                float4 u = *(const float4*)mrow;
                float4 v = *(const float4*)(mrow + 4);
                acc[i][0] *= u.x; acc[i][1] *= u.y; acc[i][2] *= u.z; acc[i][3] *= u.w;
                acc[i][4] *= v.x; acc[i][5] *= v.y; acc[i][6] *= v.z; acc[i][7] *= v.w;
            }
        }
        #pragma unroll
        for (int i = 0; i < 8; i++)
            #pragma unroll
            for (int j = 0; j < 8; j++)
                colmax[j] = fmaxf(colmax[j], acc[i][j]);
    }

    // Cross-thread (ty) max reduce in shared memory
    #pragma unroll
    for (int j = 0; j < 8; j++) red[ty][tx * 8 + j] = colmax[j];

    for (int s = 8; s >= 1; s >>= 1) {
        __syncthreads();
        if (ty < s) {
            #pragma unroll
            for (int j = 0; j < 8; j++) {
                int c = tx * 8 + j;
                red[ty][c] = fmaxf(red[ty][c], red[ty + s][c]);
            }
        }
    }
    __syncthreads();

    if (ty == 0) {
        #pragma unroll
        for (int j = 0; j < 8; j++)
            out[((size_t)b * 10 + q) * HW + n0 + tx * 8 + j] = red[0][tx * 8 + j];
    }
}

// Coarse path: 6 GEMVs, out[b, 4+i, n] = vec_i[b,:] . key[b,:,n]
__global__ __launch_bounds__(256) void coarse_kernel(
    const float* __restrict__ key,
    const float* __restrict__ obg, const float* __restrict__ ofg,
    const float* __restrict__ sbg, const float* __restrict__ sfg,
    const float* __restrict__ lobg, const float* __restrict__ lofg,
    float* __restrict__ out)
{
    const int b = blockIdx.y;
    const int n = blockIdx.x * 256 + threadIdx.x;   // HW = 9 * 256

    __shared__ float vs[6][CDIM];
    const float* vecs[6] = {obg, ofg, sbg, sfg, lobg, lofg};
    for (int idx = threadIdx.x; idx < 6 * CDIM; idx += 256) {
        int i = idx >> 9, c = idx & (CDIM - 1);
        vs[i][c] = vecs[i][(size_t)b * CDIM + c];
    }
    __syncthreads();

    const float* kb = key + (size_t)b * CDIM * HW + n;
    float acc[6] = {0.f, 0.f, 0.f, 0.f, 0.f, 0.f};
    for (int c = 0; c < CDIM; c++) {
        float kv = kb[(size_t)c * HW];
        #pragma unroll
        for (int i = 0; i < 6; i++) acc[i] = fmaf(vs[i][c], kv, acc[i]);
    }
    #pragma unroll
    for (int i = 0; i < 6; i++)
        out[((size_t)b * 10 + 4 + i) * HW + n] = acc[i];
}

extern "C" void kernel_launch(void* const* d_in, const int* in_sizes, int n_in,
                              void* d_out, int out_size)
{
    const float* key = (const float*)d_in[0];
    const float* sds = (const float*)d_in[1];
    const float* gbg = (const float*)d_in[2];
    const float* gfg = (const float*)d_in[3];
    const float* lbg = (const float*)d_in[4];
    const float* lfg = (const float*)d_in[5];
    const float* obg = (const float*)d_in[6];
    const float* ofg = (const float*)d_in[7];
    const float* sbg = (const float*)d_in[8];
    const float* sfg = (const float*)d_in[9];
    const float* lobg = (const float*)d_in[10];
    const float* lofg = (const float*)d_in[11];
    float* out = (float*)d_out;

    dim3 gf(HW / TN, 4, BATCH);
    fine_kernel<<<gf, 256>>>(key, sds, gbg, gfg, lbg, lfg, out);

    dim3 gc(HW / 256, BATCH);
    coarse_kernel<<<gc, 256>>>(key, obg, ofg, sbg, sfg, lobg, lofg, out);
}

// round 3
// speedup vs baseline: 3.0184x; 3.0184x over previous
#include <cuda_runtime.h>
#include <cuda_bf16.h>
#include <math_constants.h>
#include <cstdint>

#define HW    2304
#define CDIM  512
#define BATCH 8
#define TM    128
#define TN    128
#define KC    16          // k-chunk (two k8 mma steps)
#define NCHUNK (CDIM / KC)

__device__ __forceinline__ uint32_t f2tf(float x) {
    uint32_t r;
    asm("cvt.rna.tf32.f32 %0, %1;" : "=r"(r) : "f"(x));
    return r;
}

__device__ __forceinline__ void mma_tf32(float c[4], uint32_t a0, uint32_t a1,
                                         uint32_t a2, uint32_t a3,
                                         uint32_t b0, uint32_t b1) {
    asm volatile(
        "mma.sync.aligned.m16n8k8.row.col.f32.tf32.tf32.f32 "
        "{%0,%1,%2,%3}, {%4,%5,%6,%7}, {%8,%9}, {%0,%1,%2,%3};"
        : "+f"(c[0]), "+f"(c[1]), "+f"(c[2]), "+f"(c[3])
        : "r"(a0), "r"(a1), "r"(a2), "r"(a3), "r"(b0), "r"(b1));
}

#define CPA16(dst_sm, src) \
    asm volatile("cp.async.ca.shared.global [%0], [%1], 16;" :: "r"(dst_sm), "l"(src))

// Fine path: out[b,q,n] = max_m ( (bank[b,m,:].key[b,:,n]) * (mask[b,m,n] if q>=2) )
// CTA = (n-tile of 128, q, b). Loops 18 m-tiles; each is a 128x128x512 tf32
// tensor-core GEMM tile with fused mask + running column max.
__global__ __launch_bounds__(256, 2) void fine_kernel(
    const float* __restrict__ key,   // [B, C, HW]
    const float* __restrict__ sds,   // [B, HW, HW]
    const float* __restrict__ gbg,   // [B, HW, C]
    const float* __restrict__ gfg,
    const float* __restrict__ lbg,
    const float* __restrict__ lfg,
    float* __restrict__ out)         // [B, 10, HW]
{
    const int ntile = blockIdx.x;    // 0..17
    const int q     = blockIdx.y;    // 0..3
    const int b     = blockIdx.z;    // 0..7

    const float* bank = (q == 0) ? gbg : (q == 1) ? gfg : (q == 2) ? lbg : lfg;
    bank += (size_t)b * HW * CDIM;
    const float* k    = key + (size_t)b * CDIM * HW;
    const float* mask = sds + (size_t)b * HW * HW;
    const bool use_mask = (q >= 2);
    const int n0 = ntile * TN;

    // As[buf][m][k]  (pitch 20 -> conflict-free fragment LDS)
    // Bs[buf][k][n]  (pitch 136)
    __shared__ float As[2][TM][20];
    __shared__ float Bs[2][KC][136];
    __shared__ float red[2][TN];

    const int tid  = threadIdx.x;
    const int lane = tid & 31;
    const int wid  = tid >> 5;
    const int wm   = (wid & 1) * 64;   // warp m-offset
    const int wn   = (wid >> 1) * 32;  // warp n-offset
    const int gr   = lane >> 2;        // group row 0..7
    const int tc   = lane & 3;         // thread col 0..3

    // producer coords: per chunk each thread copies 8 contiguous A floats
    // (two 16B cp.async) and 8 B floats (two 16B cp.async)
    const int am   = tid >> 1;           // A row 0..127
    const int ak   = (tid & 1) * 8;      // A k-offset 0 or 8
    const int bk   = tid >> 4;           // B k-row 0..15
    const int bn   = (tid & 15) * 4;     // B n-offset

    float colmax[4][2];
    #pragma unroll
    for (int nt = 0; nt < 4; nt++) { colmax[nt][0] = -CUDART_INF_F; colmax[nt][1] = -CUDART_INF_F; }

    for (int m0 = 0; m0 < HW; m0 += TM) {
        float acc[4][4][4];
        #pragma unroll
        for (int mt = 0; mt < 4; mt++)
            #pragma unroll
            for (int nt = 0; nt < 4; nt++)
                #pragma unroll
                for (int i = 0; i < 4; i++) acc[mt][nt][i] = 0.0f;

        // preload chunk 0 into buffer 0
        {
            const float* asrc = &bank[(size_t)(m0 + am) * CDIM + ak];
            unsigned da0 = (unsigned)__cvta_generic_to_shared(&As[0][am][ak]);
            unsigned da1 = (unsigned)__cvta_generic_to_shared(&As[0][am][ak + 4]);
            CPA16(da0, asrc);
            CPA16(da1, asrc + 4);
            unsigned db0 = (unsigned)__cvta_generic_to_shared(&Bs[0][bk][bn]);
            unsigned db1 = (unsigned)__cvta_generic_to_shared(&Bs[0][bk][bn + 64]);
            CPA16(db0, &k[(size_t)bk * HW + n0 + bn]);
            CPA16(db1, &k[(size_t)bk * HW + n0 + bn + 64]);
            asm volatile("cp.async.commit_group;");
            asm volatile("cp.async.wait_group 0;");
        }
        __syncthreads();

        for (int c = 0; c < NCHUNK; c++) {
            const int cur = c & 1;
            // issue loads for next chunk into the other buffer
            if (c + 1 < NCHUNK) {
                const int kc = (c + 1) * KC;
                const int nb = cur ^ 1;
                const float* asrc = &bank[(size_t)(m0 + am) * CDIM + kc + ak];
                unsigned da0 = (unsigned)__cvta_generic_to_shared(&As[nb][am][ak]);
                unsigned da1 = (unsigned)__cvta_generic_to_shared(&As[nb][am][ak + 4]);
                CPA16(da0, asrc);
                CPA16(da1, asrc + 4);
                unsigned db0 = (unsigned)__cvta_generic_to_shared(&Bs[nb][bk][bn]);
                unsigned db1 = (unsigned)__cvta_generic_to_shared(&Bs[nb][bk][bn + 64]);
                CPA16(db0, &k[(size_t)(kc + bk) * HW + n0 + bn]);
                CPA16(db1, &k[(size_t)(kc + bk) * HW + n0 + bn + 64]);
                asm volatile("cp.async.commit_group;");
            }

            // two k8 mma steps from current buffer
            #pragma unroll
            for (int s = 0; s < 2; s++) {
                const int ks = s * 8;
                uint32_t a[4][4], bf[4][2];
                #pragma unroll
                for (int mt = 0; mt < 4; mt++) {
                    const int mb = wm + mt * 16 + gr;
                    a[mt][0] = f2tf(As[cur][mb][ks + tc]);
                    a[mt][1] = f2tf(As[cur][mb + 8][ks + tc]);
                    a[mt][2] = f2tf(As[cur][mb][ks + 4 + tc]);
                    a[mt][3] = f2tf(As[cur][mb + 8][ks + 4 + tc]);
                }
                #pragma unroll
                for (int nt = 0; nt < 4; nt++) {
                    const int nb = wn + nt * 8 + gr;
                    bf[nt][0] = f2tf(Bs[cur][ks + tc][nb]);
                    bf[nt][1] = f2tf(Bs[cur][ks + 4 + tc][nb]);
                }
                #pragma unroll
                for (int mt = 0; mt < 4; mt++)
                    #pragma unroll
                    for (int nt = 0; nt < 4; nt++)
                        mma_tf32(acc[mt][nt], a[mt][0], a[mt][1], a[mt][2], a[mt][3],
                                 bf[nt][0], bf[nt][1]);
            }

            asm volatile("cp.async.wait_group 0;");
            __syncthreads();
        }

        // fused epilogue: mask multiply + fold into running column max
        if (use_mask) {
            #pragma unroll
            for (int mt = 0; mt < 4; mt++) {
                const size_t r0 = (size_t)(m0 + wm + mt * 16 + gr) * HW;
                #pragma unroll
                for (int nt = 0; nt < 4; nt++) {
                    const float* mp = mask + r0 + n0 + wn + nt * 8 + 2 * tc;
                    float2 u0 = *(const float2*)mp;
                    float2 u1 = *(const float2*)(mp + (size_t)8 * HW);
                    acc[mt][nt][0] *= u0.x; acc[mt][nt][1] *= u0.y;
                    acc[mt][nt][2] *= u1.x; acc[mt][nt][3] *= u1.y;
                }
            }
        }
        #pragma unroll
        for (int mt = 0; mt < 4; mt++)
            #pragma unroll
            for (int nt = 0; nt < 4; nt++) {
                colmax[nt][0] = fmaxf(colmax[nt][0], fmaxf(acc[mt][nt][0], acc[mt][nt][2]));
                colmax[nt][1] = fmaxf(colmax[nt][1], fmaxf(acc[mt][nt][1], acc[mt][nt][3]));
            }
    }

    // cross-lane max over the 8 row-groups (lanes differing in bits 2..4)
    #pragma unroll
    for (int nt = 0; nt < 4; nt++)
        #pragma unroll
        for (int j = 0; j < 2; j++) {
            float v = colmax[nt][j];
            v = fmaxf(v, __shfl_xor_sync(0xffffffffu, v, 4));
            v = fmaxf(v, __shfl_xor_sync(0xffffffffu, v, 8));
            v = fmaxf(v, __shfl_xor_sync(0xffffffffu, v, 16));
            colmax[nt][j] = v;
        }
    if (lane < 4) {
        #pragma unroll
        for (int nt = 0; nt < 4; nt++) {
            red[wid & 1][wn + nt * 8 + 2 * lane + 0] = colmax[nt][0];
            red[wid & 1][wn + nt * 8 + 2 * lane + 1] = colmax[nt][1];
        }
    }
    __syncthreads();
    if (tid < TN)
        out[((size_t)b * 10 + q) * HW + n0 + tid] = fmaxf(red[0][tid], red[1][tid]);
}

// Coarse path: 6 GEMVs, out[b, 4+i, n] = vec_i[b,:] . key[b,:,n]
__global__ __launch_bounds__(256) void coarse_kernel(
    const float* __restrict__ key,
    const float* __restrict__ obg, const float* __restrict__ ofg,
    const float* __restrict__ sbg, const float* __restrict__ sfg,
    const float* __restrict__ lobg, const float* __restrict__ lofg,
    float* __restrict__ out)
{
    const int b = blockIdx.y;
    const int n = blockIdx.x * 256 + threadIdx.x;   // HW = 9 * 256

    __shared__ float vs[6][CDIM];
    const float* vecs[6] = {obg, ofg, sbg, sfg, lobg, lofg};
    for (int idx = threadIdx.x; idx < 6 * CDIM; idx += 256) {
        int i = idx >> 9, c = idx & (CDIM - 1);
        vs[i][c] = vecs[i][(size_t)b * CDIM + c];
    }
    __syncthreads();

    const float* kb = key + (size_t)b * CDIM * HW + n;
    float acc[6] = {0.f, 0.f, 0.f, 0.f, 0.f, 0.f};
    #pragma unroll 8
    for (int c = 0; c < CDIM; c++) {
        float kv = kb[(size_t)c * HW];
        #pragma unroll
        for (int i = 0; i < 6; i++) acc[i] = fmaf(vs[i][c], kv, acc[i]);
    }
    #pragma unroll
    for (int i = 0; i < 6; i++)
        out[((size_t)b * 10 + 4 + i) * HW + n] = acc[i];
}

extern "C" void kernel_launch(void* const* d_in, const int* in_sizes, int n_in,
                              void* d_out, int out_size)
{
    const float* key = (const float*)d_in[0];
    const float* sds = (const float*)d_in[1];
    const float* gbg = (const float*)d_in[2];
    const float* gfg = (const float*)d_in[3];
    const float* lbg = (const float*)d_in[4];
    const float* lfg = (const float*)d_in[5];
    const float* obg = (const float*)d_in[6];
    const float* ofg = (const float*)d_in[7];
    const float* sbg = (const float*)d_in[8];
    const float* sfg = (const float*)d_in[9];
    const float* lobg = (const float*)d_in[10];
    const float* lofg = (const float*)d_in[11];
    float* out = (float*)d_out;

    dim3 gf(HW / TN, 4, BATCH);
    fine_kernel<<<gf, 256>>>(key, sds, gbg, gfg, lbg, lfg, out);

    dim3 gc(HW / 256, BATCH);
    coarse_kernel<<<gc, 256>>>(key, obg, ofg, sbg, sfg, lobg, lofg, out);
}

// round 9
// speedup vs baseline: 3.4604x; 1.1464x over previous
#include <cuda_runtime.h>
#include <cuda_fp16.h>
#include <math_constants.h>
#include <cstdint>

#define HW     2304
#define CDIM   512
#define BATCH  8
#define TM     128
#define TN     128
#define KC     32              // k-chunk: two m16n8k16 steps
#define NCH    (CDIM / KC)     // 16 chunks

// ---- dynamic smem (bytes) ----
// A: fp32 [2][128][40]  (pitch 160B; 32 payload + 8 pad floats) -> 2 x 20480
// B: fp16 [2][128][40]  (pitch 80B;  32 payload + 8 pad halves) -> 2 x 10240
#define SM_A     0
#define SM_B     40960
#define SM_RED   61440          // 2 x 128 floats
#define SM_TOTAL 62464
#define A_PITCH  160            // bytes
#define B_PITCH  80             // bytes

__device__ __forceinline__ uint32_t pack_h2(float lo, float hi) {
    uint32_t r;
    asm("cvt.rn.f16x2.f32 %0, %1, %2;" : "=r"(r) : "f"(hi), "f"(lo));
    return r;
}

__device__ __forceinline__ void mma_f16(float c[4], uint32_t a0, uint32_t a1,
                                        uint32_t a2, uint32_t a3,
                                        uint32_t b0, uint32_t b1) {
    asm volatile(
        "mma.sync.aligned.m16n8k16.row.col.f32.f16.f16.f32 "
        "{%0,%1,%2,%3}, {%4,%5,%6,%7}, {%8,%9}, {%0,%1,%2,%3};"
        : "+f"(c[0]), "+f"(c[1]), "+f"(c[2]), "+f"(c[3])
        : "r"(a0), "r"(a1), "r"(a2), "r"(a3), "r"(b0), "r"(b1));
}

#define CPA16(dst_sm, src) \
    asm volatile("cp.async.ca.shared.global [%0], [%1], 16;" :: "r"(dst_sm), "l"(src))
#define CPA_COMMIT() asm volatile("cp.async.commit_group;")
#define CPA_WAIT0()  asm volatile("cp.async.wait_group 0;")

// Fine path: out[b,q,n] = max_m ( (bank[b,m,:].key[b,:,n]) * (mask[b,m,n] if q>=2) )
// CTA = (n-tile 128, q, b); 18 m-tiles of 128; fp16 tensor-core GEMM with
// fp32 accumulate, fused mask + running column max.
__global__ __launch_bounds__(256, 2) void fine_kernel(
    const float* __restrict__ key,   // [B, C, HW]
    const float* __restrict__ sds,   // [B, HW, HW]
    const float* __restrict__ gbg,   // [B, HW, C]
    const float* __restrict__ gfg,
    const float* __restrict__ lbg,
    const float* __restrict__ lfg,
    float* __restrict__ out)         // [B, 10, HW]
{
    extern __shared__ char smem[];
    const int ntile = blockIdx.x;    // 0..17
    const int q     = blockIdx.y;    // 0..3
    const int b     = blockIdx.z;    // 0..7

    const float* bank = (q == 0) ? gbg : (q == 1) ? gfg : (q == 2) ? lbg : lfg;
    bank += (size_t)b * HW * CDIM;
    const float* kp   = key + (size_t)b * CDIM * HW;
    const float* mask = sds + (size_t)b * HW * HW;
    const bool use_mask = (q >= 2);
    const int n0 = ntile * TN;

    const int tid  = threadIdx.x;
    const int lane = tid & 31;
    const int wid  = tid >> 5;
    const int wm   = (wid & 1) * 64;   // warp m-offset
    const int wn   = (wid >> 1) * 32;  // warp n-offset
    const int gr   = lane >> 2;        // group row 0..7
    const int tc   = lane & 3;         // thread col 0..3

    char* As = smem + SM_A;            // fp32, pitch A_PITCH
    char* Bs = smem + SM_B;            // fp16, pitch B_PITCH
    float* red = (float*)(smem + SM_RED);

    // producer coords
    const int arow = tid >> 1;          // 0..127
    const int ah   = tid & 1;           // k-half (16 floats)
    const int bn   = tid >> 1;          // B col 0..127
    const int bh   = tid & 1;           // k-half (16 values)

    float colmax[4][2];
    #pragma unroll
    for (int nt = 0; nt < 4; nt++) { colmax[nt][0] = -CUDART_INF_F; colmax[nt][1] = -CUDART_INF_F; }

    for (int m0 = 0; m0 < HW; m0 += TM) {
        float acc[4][4][4];
        #pragma unroll
        for (int mt = 0; mt < 4; mt++)
            #pragma unroll
            for (int nt = 0; nt < 4; nt++)
                #pragma unroll
                for (int i = 0; i < 4; i++) acc[mt][nt][i] = 0.0f;

        // ---- prologue: chunk 0 into buffer 0 ----
        {
            const float* asrc = bank + (size_t)(m0 + arow) * CDIM + ah * 16;
            uint32_t adst = (uint32_t)__cvta_generic_to_shared(As + arow * A_PITCH + ah * 64);
            #pragma unroll
            for (int j = 0; j < 4; j++) CPA16(adst + j * 16, asrc + j * 4);
            CPA_COMMIT();

            float st[16];
            const float* kb = kp + (size_t)(bh * 16) * HW + n0 + bn;
            #pragma unroll
            for (int j = 0; j < 16; j++) st[j] = kb[(size_t)j * HW];
            uint32_t h[8];
            #pragma unroll
            for (int j = 0; j < 8; j++) h[j] = pack_h2(st[2 * j], st[2 * j + 1]);
            uint4* bd = (uint4*)(Bs + bn * B_PITCH + bh * 32);
            bd[0] = make_uint4(h[0], h[1], h[2], h[3]);
            bd[1] = make_uint4(h[4], h[5], h[6], h[7]);

            CPA_WAIT0();
        }
        __syncthreads();

        for (int c = 0; c < NCH; c++) {
            const int cur = c & 1;
            float st[16];
            if (c + 1 < NCH) {
                const int kc = (c + 1) * KC;
                const int nb = cur ^ 1;
                const float* asrc = bank + (size_t)(m0 + arow) * CDIM + kc + ah * 16;
                uint32_t adst = (uint32_t)__cvta_generic_to_shared(
                    As + nb * 20480 + arow * A_PITCH + ah * 64);
                #pragma unroll
                for (int j = 0; j < 4; j++) CPA16(adst + j * 16, asrc + j * 4);
                CPA_COMMIT();
                const float* kb = kp + (size_t)(kc + bh * 16) * HW + n0 + bn;
                #pragma unroll
                for (int j = 0; j < 16; j++) st[j] = kb[(size_t)j * HW];
            }

            // ---- two m16n8k16 steps from current buffers ----
            const char* Ab = As + cur * 20480;
            const char* Bb = Bs + cur * 10240;
            #pragma unroll
            for (int ks = 0; ks < 2; ks++) {
                uint32_t a[4][4], bf[4][2];
                #pragma unroll
                for (int mt = 0; mt < 4; mt++) {
                    const char* ap = Ab + (wm + mt * 16 + gr) * A_PITCH + ks * 64 + tc * 8;
                    float2 v0 = *(const float2*)ap;
                    float2 v1 = *(const float2*)(ap + 8 * A_PITCH);
                    float2 v2 = *(const float2*)(ap + 32);
                    float2 v3 = *(const float2*)(ap + 8 * A_PITCH + 32);
                    a[mt][0] = pack_h2(v0.x, v0.y);
                    a[mt][1] = pack_h2(v1.x, v1.y);
                    a[mt][2] = pack_h2(v2.x, v2.y);
                    a[mt][3] = pack_h2(v3.x, v3.y);
                }
                #pragma unroll
                for (int nt = 0; nt < 4; nt++) {
                    const char* bp = Bb + (wn + nt * 8 + gr) * B_PITCH + ks * 32 + tc * 4;
                    bf[nt][0] = *(const uint32_t*)bp;
                    bf[nt][1] = *(const uint32_t*)(bp + 16);
                }
                #pragma unroll
                for (int mt = 0; mt < 4; mt++)
                    #pragma unroll
                    for (int nt = 0; nt < 4; nt++)
                        mma_f16(acc[mt][nt], a[mt][0], a[mt][1], a[mt][2], a[mt][3],
                                bf[nt][0], bf[nt][1]);
            }

            if (c + 1 < NCH) {
                const int nb = cur ^ 1;
                uint32_t h[8];
                #pragma unroll
                for (int j = 0; j < 8; j++) h[j] = pack_h2(st[2 * j], st[2 * j + 1]);
                uint4* bd = (uint4*)(Bs + nb * 10240 + bn * B_PITCH + bh * 32);
                bd[0] = make_uint4(h[0], h[1], h[2], h[3]);
                bd[1] = make_uint4(h[4], h[5], h[6], h[7]);
                CPA_WAIT0();
            }
            __syncthreads();
        }

        // fused epilogue: mask multiply + fold into running column max
        if (use_mask) {
            #pragma unroll
            for (int mt = 0; mt < 4; mt++) {
                const size_t r0 = (size_t)(m0 + wm + mt * 16 + gr) * HW;
                #pragma unroll
                for (int nt = 0; nt < 4; nt++) {
                    const float* mp = mask + r0 + n0 + wn + nt * 8 + 2 * tc;
                    float2 u0 = *(const float2*)mp;
                    float2 u1 = *(const float2*)(mp + (size_t)8 * HW);
                    acc[mt][nt][0] *= u0.x; acc[mt][nt][1] *= u0.y;
                    acc[mt][nt][2] *= u1.x; acc[mt][nt][3] *= u1.y;
                }
            }
        }
        #pragma unroll
        for (int mt = 0; mt < 4; mt++)
            #pragma unroll
            for (int nt = 0; nt < 4; nt++) {
                colmax[nt][0] = fmaxf(colmax[nt][0], fmaxf(acc[mt][nt][0], acc[mt][nt][2]));
                colmax[nt][1] = fmaxf(colmax[nt][1], fmaxf(acc[mt][nt][1], acc[mt][nt][3]));
            }
    }

    // cross-lane max over the 8 row-groups (lanes differing in bits 2..4)
    #pragma unroll
    for (int nt = 0; nt < 4; nt++)
        #pragma unroll
        for (int j = 0; j < 2; j++) {
            float v = colmax[nt][j];
            v = fmaxf(v, __shfl_xor_sync(0xffffffffu, v, 4));
            v = fmaxf(v, __shfl_xor_sync(0xffffffffu, v, 8));
            v = fmaxf(v, __shfl_xor_sync(0xffffffffu, v, 16));
            colmax[nt][j] = v;
        }
    if (lane < 4) {
        #pragma unroll
        for (int nt = 0; nt < 4; nt++) {
            red[(wid & 1) * TN + wn + nt * 8 + 2 * lane + 0] = colmax[nt][0];
            red[(wid & 1) * TN + wn + nt * 8 + 2 * lane + 1] = colmax[nt][1];
        }
    }
    __syncthreads();
    if (tid < TN)
        out[((size_t)b * 10 + q) * HW + n0 + tid] = fmaxf(red[tid], red[TN + tid]);
}

// Coarse path: 6 GEMVs, deterministic 2-way c-split within each block.
__global__ __launch_bounds__(256) void coarse_kernel(
    const float* __restrict__ key,
    const float* __restrict__ obg, const float* __restrict__ ofg,
    const float* __restrict__ sbg, const float* __restrict__ sfg,
    const float* __restrict__ lobg, const float* __restrict__ lofg,
    float* __restrict__ out)
{
    const int b    = blockIdx.y;
    const int nl   = threadIdx.x & 127;
    const int half = threadIdx.x >> 7;          // c-range half
    const int n    = blockIdx.x * 128 + nl;     // HW = 18 * 128

    __shared__ float vs[6][CDIM];
    __shared__ float part[2][6][128];
    const float* vecs[6] = {obg, ofg, sbg, sfg, lobg, lofg};
    for (int idx = threadIdx.x; idx < 6 * CDIM; idx += 256) {
        int i = idx >> 9, c = idx & (CDIM - 1);
        vs[i][c] = vecs[i][(size_t)b * CDIM + c];
    }
    __syncthreads();

    const float* kb = key + (size_t)b * CDIM * HW + n;
    float acc[6] = {0.f, 0.f, 0.f, 0.f, 0.f, 0.f};
    const int c0 = half * 256;
    #pragma unroll 8
    for (int c = 0; c < 256; c++) {
        float kv = kb[(size_t)(c0 + c) * HW];
        #pragma unroll
        for (int i = 0; i < 6; i++) acc[i] = fmaf(vs[i][c0 + c], kv, acc[i]);
    }
    #pragma unroll
    for (int i = 0; i < 6; i++) part[half][i][nl] = acc[i];
    __syncthreads();
    if (half == 0) {
        #pragma unroll
        for (int i = 0; i < 6; i++)
            out[((size_t)b * 10 + 4 + i) * HW + n] = part[0][i][nl] + part[1][i][nl];
    }
}

extern "C" void kernel_launch(void* const* d_in, const int* in_sizes, int n_in,
                              void* d_out, int out_size)
{
    const float* key = (const float*)d_in[0];
    const float* sds = (const float*)d_in[1];
    const float* gbg = (const float*)d_in[2];
    const float* gfg = (const float*)d_in[3];
    const float* lbg = (const float*)d_in[4];
    const float* lfg = (const float*)d_in[5];
    const float* obg = (const float*)d_in[6];
    const float* ofg = (const float*)d_in[7];
    const float* sbg = (const float*)d_in[8];
    const float* sfg = (const float*)d_in[9];
    const float* lobg = (const float*)d_in[10];
    const float* lofg = (const float*)d_in[11];
    float* out = (float*)d_out;

    cudaFuncSetAttribute(fine_kernel, cudaFuncAttributeMaxDynamicSharedMemorySize, SM_TOTAL);

    dim3 gf(HW / TN, 4, BATCH);
    fine_kernel<<<gf, 256, SM_TOTAL>>>(key, sds, gbg, gfg, lbg, lfg, out);

    dim3 gc(HW / 128, BATCH);
    coarse_kernel<<<gc, 256>>>(key, obg, ofg, sbg, sfg, lobg, lofg, out);
}